// round 8
// baseline (speedup 1.0000x reference)
#include <cuda_runtime.h>
#include <cuda_bf16.h>
#include <math.h>

// ---------------- Problem dims ----------------
#define NL    8
#define BSZ   8
#define LSEQ  1024
#define DM    256
#define DI    512
#define NST   16
#define DTR   16
#define PROJC 48
#define MROWS (BSZ*LSEQ)  // 8192

// ---------------- Device scratch ----------------
__device__ float g_h   [MROWS*DM];
__device__ float g_xz  [MROWS*2*DI];
__device__ float g_u   [MROWS*DI];
__device__ float g_proj[MROWS*PROJC];
__device__ float g_ymod[MROWS*DI];
__device__ float g_out2[MROWS*DM];
__device__ float g_pooled[BSZ*DM];

// ---------------- helpers ----------------
__device__ __forceinline__ void mma_tf32(float& d0, float& d1, float& d2, float& d3,
                                         unsigned a0, unsigned a1, unsigned a2, unsigned a3,
                                         unsigned b0, unsigned b1) {
    asm volatile(
        "mma.sync.aligned.m16n8k8.row.col.f32.tf32.tf32.f32 "
        "{%0,%1,%2,%3}, {%4,%5,%6,%7}, {%8,%9}, {%0,%1,%2,%3};\n"
        : "+f"(d0), "+f"(d1), "+f"(d2), "+f"(d3)
        : "r"(a0), "r"(a1), "r"(a2), "r"(a3), "r"(b0), "r"(b1));
}
__device__ __forceinline__ void cp16(unsigned dst, const void* src) {
    asm volatile("cp.async.cg.shared.global [%0], [%1], 16;\n" :: "r"(dst), "l"(src));
}
__device__ __forceinline__ void cp_commit() { asm volatile("cp.async.commit_group;\n"); }
__device__ __forceinline__ void cp_wait0()  { asm volatile("cp.async.wait_group 0;\n"); }
__device__ __forceinline__ void cp_wait1()  { asm volatile("cp.async.wait_group 1;\n"); }
__device__ __forceinline__ void cp_wait2()  { asm volatile("cp.async.wait_group 2;\n"); }

// ---------------- Encoder ----------------
__global__ void enc_kernel(const float* __restrict__ x,
                           const float* __restrict__ w,
                           const float* __restrict__ bb) {
    int bl = blockIdx.x;
    int m  = threadIdx.x;
    int b = bl >> 10, l = bl & 1023;
    float acc = bb[m];
#pragma unroll
    for (int c = 0; c < 3; c++)
        acc = fmaf(x[(b*3 + c)*LSEQ + l], w[c*DM + m], acc);
    g_h[bl*DM + m] = acc;
}

// ---------------- TF32 GEMM, cp.async 4-stage pipeline, 4 blocks/SM ----------------
// Tile 64x64x16, 256 threads (8 warps: 4m x 2n), warp tile 16x32.
// M%64==0, K%16==0, N guarded. fp32 bits fed as tf32 (RZ).
#define ASTR 20
#define BSTR 72
__global__ void __launch_bounds__(256, 4)
gemm_tf32_cp(const float* __restrict__ A,
             const float* __restrict__ B,
             float* __restrict__ C,
             int M, int N, int K) {
    __shared__ unsigned As[4][64*ASTR];    // 20.5 KB
    __shared__ unsigned Bs[4][16*BSTR];    // 18.4 KB

    const int tid  = threadIdx.x;
    const int lane = tid & 31;
    const int wid  = tid >> 5;
    const int wm   = wid & 3;
    const int wn   = wid >> 2;
    const int m0   = blockIdx.y * 64;
    const int n0   = blockIdx.x * 64;
    const int r = lane >> 2;
    const int c = lane & 3;

    if (n0 + 64 > N) {
#pragma unroll
        for (int s = 0; s < 4; s++)
            for (int i = tid; i < 16*BSTR; i += 256)
                Bs[s][i] = 0u;
        __syncthreads();
    }

    const int aRow = tid >> 2;             // 64 rows, 4 quads each
    const int aKq  = tid & 3;
    const int bRow = tid >> 4;
    const int bNq  = tid & 15;
    const bool bOk = (n0 + bNq*4 + 3) < N;

    unsigned aBase[4], bBase[4];
#pragma unroll
    for (int s = 0; s < 4; s++) {
        aBase[s] = (unsigned)__cvta_generic_to_shared(&As[s][0]);
        bBase[s] = (unsigned)__cvta_generic_to_shared(&Bs[s][0]);
    }

    auto loadTile = [&](int t, int s) {
        int k0 = t * 16;
        cp16(aBase[s] + (aRow*ASTR + aKq*4)*4,
             A + (size_t)(m0 + aRow)*K + k0 + aKq*4);
        if (bOk)
            cp16(bBase[s] + (bRow*BSTR + bNq*4)*4,
                 B + (size_t)(k0 + bRow)*N + n0 + bNq*4);
        cp_commit();
    };

    float acc[4][4] = {};
    const int T = K >> 4;

    loadTile(0, 0); loadTile(1, 1); loadTile(2, 2);

    for (int t = 0; t < T; t++) {
        int cur = t & 3;
        cp_wait2();
        __syncthreads();
        if (t + 3 < T) loadTile(t + 3, (t + 3) & 3);
        else           cp_commit();        // keep wait_group arithmetic exact

        const unsigned* Ab = As[cur];
        const unsigned* Bb = Bs[cur];
#pragma unroll
        for (int kk = 0; kk < 16; kk += 8) {
            unsigned af[4], bf[4][2];
            {
                int mrow = wm*16;
                af[0] = Ab[(mrow + r    )*ASTR + kk + c    ];
                af[1] = Ab[(mrow + r + 8)*ASTR + kk + c    ];
                af[2] = Ab[(mrow + r    )*ASTR + kk + c + 4];
                af[3] = Ab[(mrow + r + 8)*ASTR + kk + c + 4];
            }
#pragma unroll
            for (int bn = 0; bn < 4; bn++) {
                int ncol = wn*32 + bn*8 + r;
                bf[bn][0] = Bb[(kk + c    )*BSTR + ncol];
                bf[bn][1] = Bb[(kk + c + 4)*BSTR + ncol];
            }
#pragma unroll
            for (int bn = 0; bn < 4; bn++)
                mma_tf32(acc[bn][0], acc[bn][1], acc[bn][2], acc[bn][3],
                         af[0], af[1], af[2], af[3],
                         bf[bn][0], bf[bn][1]);
        }
    }

#pragma unroll
    for (int bn = 0; bn < 4; bn++) {
        int m = m0 + wm*16 + r;
        int n = n0 + wn*32 + bn*8 + 2*c;
        if (n + 1 < N) {
            *(float2*)(C + (size_t)m*N + n)       = make_float2(acc[bn][0], acc[bn][1]);
            *(float2*)(C + (size_t)(m + 8)*N + n) = make_float2(acc[bn][2], acc[bn][3]);
        } else if (n < N) {
            C[(size_t)m*N + n]       = acc[bn][0];
            C[(size_t)(m + 8)*N + n] = acc[bn][2];
        }
    }
}

// ---------------- Causal depthwise conv (K=4) + SiLU ----------------
__global__ void conv_silu_kernel(const float* __restrict__ cw,
                                 const float* __restrict__ cb) {
    int d = threadIdx.x;
    int t = blockIdx.x;
    int b = t >> 8, lt = t & 255;
    int l0 = lt * 4;
    float w0 = cw[d*4+0], w1 = cw[d*4+1], w2 = cw[d*4+2], w3 = cw[d*4+3];
    float bias = cb[d];
    float v[7];
#pragma unroll
    for (int j = 0; j < 7; j++) {
        int ll = l0 - 3 + j;
        v[j] = (ll >= 0) ? g_xz[(size_t)((b << 10) + ll)*(2*DI) + d] : 0.f;
    }
#pragma unroll
    for (int i = 0; i < 4; i++) {
        float acc = bias;
        acc = fmaf(v[i],   w0, acc);
        acc = fmaf(v[i+1], w1, acc);
        acc = fmaf(v[i+2], w2, acc);
        acc = fmaf(v[i+3], w3, acc);
        float s = acc / (1.f + __expf(-acc));
        g_u[(size_t)((b << 10) + l0 + i)*DI + d] = s;
    }
}

// ---------------- Fused dt + selective scan + gate, cp.async staged ----------------
#define SCH 64
#define SPSTR 52
__global__ void __launch_bounds__(256)
scan_kernel(const float* __restrict__ A_log,
            const float* __restrict__ Dv,
            const float* __restrict__ dtw,
            const float* __restrict__ dtb) {
    __shared__ float sp[2][SCH*SPSTR];
    __shared__ float su[2][SCH*16];
    __shared__ float sz[2][SCH*16];
    __shared__ float so[SCH*16];

    const int b  = blockIdx.x >> 5;
    const int d0 = (blockIdx.x & 31) * 16;
    const int tid = threadIdx.x;
    const int hw = tid >> 4;
    const int n  = tid & 15;
    const int d  = d0 + hw;
    const int lane = tid & 31;
    const int hbase = lane & 16;
    const int blbase = b << 10;

    const int rl = tid >> 2;
    const int rq = tid & 3;

    unsigned spB[2], suB[2], szB[2];
#pragma unroll
    for (int s = 0; s < 2; s++) {
        spB[s] = (unsigned)__cvta_generic_to_shared(&sp[s][0]);
        suB[s] = (unsigned)__cvta_generic_to_shared(&su[s][0]);
        szB[s] = (unsigned)__cvta_generic_to_shared(&sz[s][0]);
    }

    auto loadChunk = [&](int c0, int buf) {
        cp16(suB[buf] + (rl*16 + rq*4)*4,
             g_u + (size_t)(blbase + c0 + rl)*DI + d0 + rq*4);
        cp16(szB[buf] + (rl*16 + rq*4)*4,
             g_xz + (size_t)(blbase + c0 + rl)*(2*DI) + DI + d0 + rq*4);
#pragma unroll
        for (int k = 0; k < 3; k++) {
            int s = tid + k*256;
            int l = s / 12, q = s - l*12;
            cp16(spB[buf] + (l*SPSTR + q*4)*4,
                 g_proj + (size_t)(blbase + c0 + l)*PROJC + q*4);
        }
        cp_commit();
    };

    float wdt[DTR];
#pragma unroll
    for (int r = 0; r < DTR; r++) wdt[r] = dtw[r*DI + d];
    const float dtbv = dtb[d];
    const float Ad = -__expf(A_log[d*NST + n]);
    const float Dd = Dv[d];
    float state = 0.f;

    loadChunk(0, 0);

    for (int cc = 0; cc < LSEQ/SCH; cc++) {
        int buf = cc & 1;
        if (cc + 1 < LSEQ/SCH) { loadChunk((cc+1)*SCH, buf ^ 1); cp_wait1(); }
        else                   { cp_wait0(); }
        __syncthreads();

        const float* P = sp[buf];
        const float* U = su[buf];
        const float* Z = sz[buf];

        float dtv4[4];
#pragma unroll
        for (int j = 0; j < 4; j++) {
            float a = dtbv;
            const float* row = &P[(j*16 + n)*SPSTR];
#pragma unroll
            for (int r = 0; r < DTR; r++) a = fmaf(row[r], wdt[r], a);
            dtv4[j] = (a > 20.f) ? a : log1pf(__expf(a));
        }

#pragma unroll 4
        for (int l = 0; l < SCH; l++) {
            float dtv = __shfl_sync(0xffffffffu, dtv4[l >> 4], hbase + (l & 15), 32);
            float uv = U[l*16 + hw];
            float Bv = P[l*SPSTR + DTR + n];
            float Cv = P[l*SPSTR + DTR + NST + n];
            state = fmaf(__expf(dtv*Ad), state, dtv*uv*Bv);
            float p = state * Cv;
            p += __shfl_xor_sync(0xffffffffu, p, 8);
            p += __shfl_xor_sync(0xffffffffu, p, 4);
            p += __shfl_xor_sync(0xffffffffu, p, 2);
            p += __shfl_xor_sync(0xffffffffu, p, 1);
            if (n == 0) {
                float zv = Z[l*16 + hw];
                float sz_ = zv / (1.f + __expf(-zv));
                so[l*16 + hw] = (p + uv*Dd) * sz_;
            }
        }
        __syncthreads();

        {
            float4 v = *(const float4*)&so[rl*16 + rq*4];
            *(float4*)(g_ymod + (size_t)(blbase + cc*SCH + rl)*DI + d0 + rq*4) = v;
        }
    }
}

// ---------------- Residual add + LayerNorm ----------------
__global__ void ln_kernel(const float* __restrict__ gamma,
                          const float* __restrict__ beta) {
    __shared__ float s1[8], s2[8];
    int bl = blockIdx.x;
    int m  = threadIdx.x;
    float t = g_out2[bl*DM + m] + g_h[bl*DM + m];
    float v1 = t, v2 = t*t;
#pragma unroll
    for (int o = 16; o > 0; o >>= 1) {
        v1 += __shfl_xor_sync(0xffffffffu, v1, o);
        v2 += __shfl_xor_sync(0xffffffffu, v2, o);
    }
    if ((m & 31) == 0) { s1[m >> 5] = v1; s2[m >> 5] = v2; }
    __syncthreads();
    float sum = 0.f, sq = 0.f;
#pragma unroll
    for (int i = 0; i < 8; i++) { sum += s1[i]; sq += s2[i]; }
    float mean = sum * (1.f/DM);
    float var  = sq * (1.f/DM) - mean*mean;
    float rs = rsqrtf(var + 1e-5f);
    g_h[bl*DM + m] = (t - mean) * rs * gamma[m] + beta[m];
}

// ---------------- Mean pool ----------------
__global__ void pool_kernel() {
    int b = blockIdx.x;
    int m = threadIdx.x;
    float s = 0.f;
    for (int l = 0; l < LSEQ; l++)
        s += g_h[(size_t)((b << 10) + l)*DM + m];
    g_pooled[b*DM + m] = s * (1.f/LSEQ);
}

// ---------------- Decoder ----------------
__global__ void dec_kernel(const float* __restrict__ w,
                           const float* __restrict__ bb,
                           float* __restrict__ out) {
    int i = threadIdx.x;
    if (i < BSZ*10) {
        int b = i / 10, o = i % 10;
        float acc = bb[o];
#pragma unroll 8
        for (int m = 0; m < DM; m++)
            acc = fmaf(g_pooled[b*DM + m], w[m*10 + o], acc);
        out[i] = acc;
    }
}

// ---------------- Launch ----------------
extern "C" void kernel_launch(void* const* d_in, const int* in_sizes, int n_in,
                              void* d_out, int out_size) {
    const float* x         = (const float*)d_in[0];
    const float* enc_w     = (const float*)d_in[1];
    const float* enc_b     = (const float*)d_in[2];
    const float* in_proj_w = (const float*)d_in[3];
    const float* conv_w    = (const float*)d_in[4];
    const float* conv_b    = (const float*)d_in[5];
    const float* x_proj_w  = (const float*)d_in[6];
    const float* dt_w      = (const float*)d_in[7];
    const float* dt_b      = (const float*)d_in[8];
    const float* A_log     = (const float*)d_in[9];
    const float* Dv        = (const float*)d_in[10];
    const float* out_proj_w= (const float*)d_in[11];
    const float* ln_g      = (const float*)d_in[12];
    const float* ln_b      = (const float*)d_in[13];
    const float* dec_w     = (const float*)d_in[14];
    const float* dec_b     = (const float*)d_in[15];

    float *p_h, *p_xz, *p_u, *p_proj, *p_ymod, *p_out2;
    cudaGetSymbolAddress((void**)&p_h,    g_h);
    cudaGetSymbolAddress((void**)&p_xz,   g_xz);
    cudaGetSymbolAddress((void**)&p_u,    g_u);
    cudaGetSymbolAddress((void**)&p_proj, g_proj);
    cudaGetSymbolAddress((void**)&p_ymod, g_ymod);
    cudaGetSymbolAddress((void**)&p_out2, g_out2);

    enc_kernel<<<MROWS, DM>>>(x, enc_w, enc_b);

    for (int i = 0; i < NL; i++) {
        // xz = h @ in_proj_w[i]   (8192x256 @ 256x1024)
        gemm_tf32_cp<<<dim3((2*DI)/64, MROWS/64), 256>>>(
            p_h, in_proj_w + (size_t)i*DM*2*DI, p_xz, MROWS, 2*DI, DM);

        conv_silu_kernel<<<BSZ*256, DI>>>(conv_w + (size_t)i*DI*4, conv_b + (size_t)i*DI);

        // proj = u @ x_proj_w[i]  (8192x512 @ 512x48)
        gemm_tf32_cp<<<dim3(1, MROWS/64), 256>>>(
            p_u, x_proj_w + (size_t)i*DI*PROJC, p_proj, MROWS, PROJC, DI);

        scan_kernel<<<BSZ*32, 256>>>(A_log + (size_t)i*DI*NST, Dv + (size_t)i*DI,
                                     dt_w + (size_t)i*DTR*DI, dt_b + (size_t)i*DI);

        // out2 = ymod @ out_proj_w[i]  (8192x512 @ 512x256)
        gemm_tf32_cp<<<dim3(DM/64, MROWS/64), 256>>>(
            p_ymod, out_proj_w + (size_t)i*DI*DM, p_out2, MROWS, DM, DI);

        ln_kernel<<<MROWS, DM>>>(ln_g + (size_t)i*DM, ln_b + (size_t)i*DM);
    }

    pool_kernel<<<BSZ, DM>>>();
    dec_kernel<<<1, 128>>>(dec_w, dec_b, (float*)d_out);
}

// round 9
// speedup vs baseline: 1.0387x; 1.0387x over previous
#include <cuda_runtime.h>
#include <cuda_bf16.h>
#include <math.h>

// ---------------- Problem dims ----------------
#define NL    8
#define BSZ   8
#define LSEQ  1024
#define DM    256
#define DI    512
#define NST   16
#define DTR   16
#define PROJC 48
#define MROWS (BSZ*LSEQ)  // 8192

// ---------------- Device scratch ----------------
__device__ float g_h   [MROWS*DM];
__device__ float g_xz  [MROWS*2*DI];
__device__ float g_u   [MROWS*DI];
__device__ float g_proj[MROWS*PROJC];
__device__ float g_ymod[MROWS*DI];
__device__ float g_out2[MROWS*DM];
__device__ float g_pooled[BSZ*DM];

// ---------------- helpers ----------------
__device__ __forceinline__ void mma_tf32(float& d0, float& d1, float& d2, float& d3,
                                         unsigned a0, unsigned a1, unsigned a2, unsigned a3,
                                         unsigned b0, unsigned b1) {
    asm volatile(
        "mma.sync.aligned.m16n8k8.row.col.f32.tf32.tf32.f32 "
        "{%0,%1,%2,%3}, {%4,%5,%6,%7}, {%8,%9}, {%0,%1,%2,%3};\n"
        : "+f"(d0), "+f"(d1), "+f"(d2), "+f"(d3)
        : "r"(a0), "r"(a1), "r"(a2), "r"(a3), "r"(b0), "r"(b1));
}
__device__ __forceinline__ void cp16(unsigned dst, const void* src) {
    asm volatile("cp.async.cg.shared.global [%0], [%1], 16;\n" :: "r"(dst), "l"(src));
}
__device__ __forceinline__ void cp_commit() { asm volatile("cp.async.commit_group;\n"); }
__device__ __forceinline__ void cp_wait0()  { asm volatile("cp.async.wait_group 0;\n"); }
__device__ __forceinline__ void cp_wait1()  { asm volatile("cp.async.wait_group 1;\n"); }
__device__ __forceinline__ void cp_wait2()  { asm volatile("cp.async.wait_group 2;\n"); }

// ---------------- No-op (profiling slot alignment) ----------------
__global__ void noop_kernel() {}

// ---------------- Encoder ----------------
__global__ void enc_kernel(const float* __restrict__ x,
                           const float* __restrict__ w,
                           const float* __restrict__ bb) {
    int bl = blockIdx.x;
    int m  = threadIdx.x;
    int b = bl >> 10, l = bl & 1023;
    float acc = bb[m];
#pragma unroll
    for (int c = 0; c < 3; c++)
        acc = fmaf(x[(b*3 + c)*LSEQ + l], w[c*DM + m], acc);
    g_h[bl*DM + m] = acc;
}

// ---------------- TF32 GEMM, cp.async 4-stage pipeline ----------------
// Tile BMx64x16, 256 threads (8 warps: 4m x 2n), warp tile (BM/4)x32.
// M%BM==0, K%16==0, N guarded. fp32 bits fed as tf32 (RZ).
#define ASTR 20
#define BSTR 72
template<int BM>
__global__ void __launch_bounds__(256, 2)
gemm_tf32_cp(const float* __restrict__ A,
             const float* __restrict__ B,
             float* __restrict__ C,
             int M, int N, int K) {
    constexpr int AM = BM / 64;
    __shared__ unsigned As[4][BM*ASTR];
    __shared__ unsigned Bs[4][16*BSTR];

    const int tid  = threadIdx.x;
    const int lane = tid & 31;
    const int wid  = tid >> 5;
    const int wm   = wid & 3;
    const int wn   = wid >> 2;
    const int m0   = blockIdx.y * BM;
    const int n0   = blockIdx.x * 64;
    const int r = lane >> 2;
    const int c = lane & 3;

    if (n0 + 64 > N) {
#pragma unroll
        for (int s = 0; s < 4; s++)
            for (int i = tid; i < 16*BSTR; i += 256)
                Bs[s][i] = 0u;
        __syncthreads();
    }

    const int bRow = tid >> 4;
    const int bNq  = tid & 15;
    const bool bOk = (n0 + bNq*4 + 3) < N;

    unsigned aBase[4], bBase[4];
#pragma unroll
    for (int s = 0; s < 4; s++) {
        aBase[s] = (unsigned)__cvta_generic_to_shared(&As[s][0]);
        bBase[s] = (unsigned)__cvta_generic_to_shared(&Bs[s][0]);
    }

    auto loadTile = [&](int t, int s) {
        int k0 = t * 16;
#pragma unroll
        for (int j = 0; j < AM; j++) {
            int slot = j*256 + tid;
            int row = slot >> 2, kq = slot & 3;
            cp16(aBase[s] + (row*ASTR + kq*4)*4,
                 A + (size_t)(m0 + row)*K + k0 + kq*4);
        }
        if (bOk)
            cp16(bBase[s] + (bRow*BSTR + bNq*4)*4,
                 B + (size_t)(k0 + bRow)*N + n0 + bNq*4);
        cp_commit();
    };

    float acc[AM][4][4] = {};
    const int T = K >> 4;

    loadTile(0, 0); loadTile(1, 1); loadTile(2, 2);

    for (int t = 0; t < T; t++) {
        int cur = t & 3;
        cp_wait2();
        __syncthreads();
        if (t + 3 < T) loadTile(t + 3, (t + 3) & 3);
        else           cp_commit();

        const unsigned* Ab = As[cur];
        const unsigned* Bb = Bs[cur];
#pragma unroll
        for (int kk = 0; kk < 16; kk += 8) {
            unsigned af[AM][4], bf[4][2];
#pragma unroll
            for (int am = 0; am < AM; am++) {
                int mrow = wm*(BM/4) + am*16;
                af[am][0] = Ab[(mrow + r    )*ASTR + kk + c    ];
                af[am][1] = Ab[(mrow + r + 8)*ASTR + kk + c    ];
                af[am][2] = Ab[(mrow + r    )*ASTR + kk + c + 4];
                af[am][3] = Ab[(mrow + r + 8)*ASTR + kk + c + 4];
            }
#pragma unroll
            for (int bn = 0; bn < 4; bn++) {
                int ncol = wn*32 + bn*8 + r;
                bf[bn][0] = Bb[(kk + c    )*BSTR + ncol];
                bf[bn][1] = Bb[(kk + c + 4)*BSTR + ncol];
            }
#pragma unroll
            for (int am = 0; am < AM; am++)
#pragma unroll
                for (int bn = 0; bn < 4; bn++)
                    mma_tf32(acc[am][bn][0], acc[am][bn][1], acc[am][bn][2], acc[am][bn][3],
                             af[am][0], af[am][1], af[am][2], af[am][3],
                             bf[bn][0], bf[bn][1]);
        }
    }

#pragma unroll
    for (int am = 0; am < AM; am++) {
#pragma unroll
        for (int bn = 0; bn < 4; bn++) {
            int m = m0 + wm*(BM/4) + am*16 + r;
            int n = n0 + wn*32 + bn*8 + 2*c;
            if (n + 1 < N) {
                *(float2*)(C + (size_t)m*N + n)       = make_float2(acc[am][bn][0], acc[am][bn][1]);
                *(float2*)(C + (size_t)(m + 8)*N + n) = make_float2(acc[am][bn][2], acc[am][bn][3]);
            } else if (n < N) {
                C[(size_t)m*N + n]       = acc[am][bn][0];
                C[(size_t)(m + 8)*N + n] = acc[am][bn][2];
            }
        }
    }
}

// ---------------- Causal depthwise conv (K=4) + SiLU ----------------
__global__ void conv_silu_kernel(const float* __restrict__ cw,
                                 const float* __restrict__ cb) {
    int d = threadIdx.x;
    int t = blockIdx.x;
    int b = t >> 8, lt = t & 255;
    int l0 = lt * 4;
    float w0 = cw[d*4+0], w1 = cw[d*4+1], w2 = cw[d*4+2], w3 = cw[d*4+3];
    float bias = cb[d];
    float v[7];
#pragma unroll
    for (int j = 0; j < 7; j++) {
        int ll = l0 - 3 + j;
        v[j] = (ll >= 0) ? g_xz[(size_t)((b << 10) + ll)*(2*DI) + d] : 0.f;
    }
#pragma unroll
    for (int i = 0; i < 4; i++) {
        float acc = bias;
        acc = fmaf(v[i],   w0, acc);
        acc = fmaf(v[i+1], w1, acc);
        acc = fmaf(v[i+2], w2, acc);
        acc = fmaf(v[i+3], w3, acc);
        float s = acc / (1.f + __expf(-acc));
        g_u[(size_t)((b << 10) + l0 + i)*DI + d] = s;
    }
}

// ---------------- Fused dt + selective scan + gate, cp.async staged ----------------
#define SCH 64
#define SPSTR 52
__global__ void __launch_bounds__(256)
scan_kernel(const float* __restrict__ A_log,
            const float* __restrict__ Dv,
            const float* __restrict__ dtw,
            const float* __restrict__ dtb) {
    __shared__ float sp[2][SCH*SPSTR];
    __shared__ float su[2][SCH*16];
    __shared__ float sz[2][SCH*16];
    __shared__ float so[SCH*16];

    const int b  = blockIdx.x >> 5;
    const int d0 = (blockIdx.x & 31) * 16;
    const int tid = threadIdx.x;
    const int hw = tid >> 4;
    const int n  = tid & 15;
    const int d  = d0 + hw;
    const int lane = tid & 31;
    const int hbase = lane & 16;
    const int blbase = b << 10;

    const int rl = tid >> 2;
    const int rq = tid & 3;

    unsigned spB[2], suB[2], szB[2];
#pragma unroll
    for (int s = 0; s < 2; s++) {
        spB[s] = (unsigned)__cvta_generic_to_shared(&sp[s][0]);
        suB[s] = (unsigned)__cvta_generic_to_shared(&su[s][0]);
        szB[s] = (unsigned)__cvta_generic_to_shared(&sz[s][0]);
    }

    auto loadChunk = [&](int c0, int buf) {
        cp16(suB[buf] + (rl*16 + rq*4)*4,
             g_u + (size_t)(blbase + c0 + rl)*DI + d0 + rq*4);
        cp16(szB[buf] + (rl*16 + rq*4)*4,
             g_xz + (size_t)(blbase + c0 + rl)*(2*DI) + DI + d0 + rq*4);
#pragma unroll
        for (int k = 0; k < 3; k++) {
            int s = tid + k*256;
            int l = s / 12, q = s - l*12;
            cp16(spB[buf] + (l*SPSTR + q*4)*4,
                 g_proj + (size_t)(blbase + c0 + l)*PROJC + q*4);
        }
        cp_commit();
    };

    float wdt[DTR];
#pragma unroll
    for (int r = 0; r < DTR; r++) wdt[r] = dtw[r*DI + d];
    const float dtbv = dtb[d];
    const float Ad = -__expf(A_log[d*NST + n]);
    const float Dd = Dv[d];
    float state = 0.f;

    loadChunk(0, 0);

    for (int cc = 0; cc < LSEQ/SCH; cc++) {
        int buf = cc & 1;
        if (cc + 1 < LSEQ/SCH) { loadChunk((cc+1)*SCH, buf ^ 1); cp_wait1(); }
        else                   { cp_wait0(); }
        __syncthreads();

        const float* P = sp[buf];
        const float* U = su[buf];
        const float* Z = sz[buf];

        float dtv4[4];
#pragma unroll
        for (int j = 0; j < 4; j++) {
            float a = dtbv;
            const float* row = &P[(j*16 + n)*SPSTR];
#pragma unroll
            for (int r = 0; r < DTR; r++) a = fmaf(row[r], wdt[r], a);
            dtv4[j] = (a > 20.f) ? a : log1pf(__expf(a));
        }

#pragma unroll 4
        for (int l = 0; l < SCH; l++) {
            float dtv = __shfl_sync(0xffffffffu, dtv4[l >> 4], hbase + (l & 15), 32);
            float uv = U[l*16 + hw];
            float Bv = P[l*SPSTR + DTR + n];
            float Cv = P[l*SPSTR + DTR + NST + n];
            state = fmaf(__expf(dtv*Ad), state, dtv*uv*Bv);
            float p = state * Cv;
            p += __shfl_xor_sync(0xffffffffu, p, 8);
            p += __shfl_xor_sync(0xffffffffu, p, 4);
            p += __shfl_xor_sync(0xffffffffu, p, 2);
            p += __shfl_xor_sync(0xffffffffu, p, 1);
            if (n == 0) {
                float zv = Z[l*16 + hw];
                float sz_ = zv / (1.f + __expf(-zv));
                so[l*16 + hw] = (p + uv*Dd) * sz_;
            }
        }
        __syncthreads();

        {
            float4 v = *(const float4*)&so[rl*16 + rq*4];
            *(float4*)(g_ymod + (size_t)(blbase + cc*SCH + rl)*DI + d0 + rq*4) = v;
        }
    }
}

// ---------------- Residual add + LayerNorm: warp-per-row, float4 ----------------
__global__ void __launch_bounds__(512)
ln_kernel(const float* __restrict__ gamma,
          const float* __restrict__ beta) {
    int wid  = threadIdx.x >> 5;
    int lane = threadIdx.x & 31;
    int bl   = blockIdx.x * 16 + wid;
    int col  = lane * 8;

    const float4* o4 = (const float4*)(g_out2 + (size_t)bl*DM + col);
    const float4* h4 = (const float4*)(g_h    + (size_t)bl*DM + col);
    float t[8];
    float4 a = o4[0], b = h4[0];
    t[0]=a.x+b.x; t[1]=a.y+b.y; t[2]=a.z+b.z; t[3]=a.w+b.w;
    a = o4[1]; b = h4[1];
    t[4]=a.x+b.x; t[5]=a.y+b.y; t[6]=a.z+b.z; t[7]=a.w+b.w;

    float v1 = 0.f, v2 = 0.f;
#pragma unroll
    for (int i = 0; i < 8; i++) { v1 += t[i]; v2 = fmaf(t[i], t[i], v2); }
#pragma unroll
    for (int o = 16; o > 0; o >>= 1) {
        v1 += __shfl_xor_sync(0xffffffffu, v1, o);
        v2 += __shfl_xor_sync(0xffffffffu, v2, o);
    }
    float mean = v1 * (1.f/DM);
    float var  = v2 * (1.f/DM) - mean*mean;
    float rs = rsqrtf(var + 1e-5f);

    float4 g0 = *(const float4*)(gamma + col);
    float4 g1 = *(const float4*)(gamma + col + 4);
    float4 b0 = *(const float4*)(beta  + col);
    float4 b1 = *(const float4*)(beta  + col + 4);

    float4 r0, r1;
    r0.x = (t[0]-mean)*rs*g0.x + b0.x;
    r0.y = (t[1]-mean)*rs*g0.y + b0.y;
    r0.z = (t[2]-mean)*rs*g0.z + b0.z;
    r0.w = (t[3]-mean)*rs*g0.w + b0.w;
    r1.x = (t[4]-mean)*rs*g1.x + b1.x;
    r1.y = (t[5]-mean)*rs*g1.y + b1.y;
    r1.z = (t[6]-mean)*rs*g1.z + b1.z;
    r1.w = (t[7]-mean)*rs*g1.w + b1.w;

    float4* out4 = (float4*)(g_h + (size_t)bl*DM + col);
    out4[0] = r0;
    out4[1] = r1;
}

// ---------------- Mean pool ----------------
__global__ void pool_kernel() {
    int b = blockIdx.x;
    int m = threadIdx.x;
    float s = 0.f;
    for (int l = 0; l < LSEQ; l++)
        s += g_h[(size_t)((b << 10) + l)*DM + m];
    g_pooled[b*DM + m] = s * (1.f/LSEQ);
}

// ---------------- Decoder ----------------
__global__ void dec_kernel(const float* __restrict__ w,
                           const float* __restrict__ bb,
                           float* __restrict__ out) {
    int i = threadIdx.x;
    if (i < BSZ*10) {
        int b = i / 10, o = i % 10;
        float acc = bb[o];
#pragma unroll 8
        for (int m = 0; m < DM; m++)
            acc = fmaf(g_pooled[b*DM + m], w[m*10 + o], acc);
        out[i] = acc;
    }
}

// ---------------- Launch ----------------
extern "C" void kernel_launch(void* const* d_in, const int* in_sizes, int n_in,
                              void* d_out, int out_size) {
    const float* x         = (const float*)d_in[0];
    const float* enc_w     = (const float*)d_in[1];
    const float* enc_b     = (const float*)d_in[2];
    const float* in_proj_w = (const float*)d_in[3];
    const float* conv_w    = (const float*)d_in[4];
    const float* conv_b    = (const float*)d_in[5];
    const float* x_proj_w  = (const float*)d_in[6];
    const float* dt_w      = (const float*)d_in[7];
    const float* dt_b      = (const float*)d_in[8];
    const float* A_log     = (const float*)d_in[9];
    const float* Dv        = (const float*)d_in[10];
    const float* out_proj_w= (const float*)d_in[11];
    const float* ln_g      = (const float*)d_in[12];
    const float* ln_b      = (const float*)d_in[13];
    const float* dec_w     = (const float*)d_in[14];
    const float* dec_b     = (const float*)d_in[15];

    float *p_h, *p_xz, *p_u, *p_proj, *p_ymod, *p_out2;
    cudaGetSymbolAddress((void**)&p_h,    g_h);
    cudaGetSymbolAddress((void**)&p_xz,   g_xz);
    cudaGetSymbolAddress((void**)&p_u,    g_u);
    cudaGetSymbolAddress((void**)&p_proj, g_proj);
    cudaGetSymbolAddress((void**)&p_ymod, g_ymod);
    cudaGetSymbolAddress((void**)&p_out2, g_out2);

    // profiling slot alignment: ncu lands on our 4th launch -> make it in_proj
    noop_kernel<<<1, 32>>>();
    noop_kernel<<<1, 32>>>();

    enc_kernel<<<MROWS, DM>>>(x, enc_w, enc_b);

    for (int i = 0; i < NL; i++) {
        // xz = h @ in_proj_w[i]   (8192x256 @ 256x1024)
        gemm_tf32_cp<128><<<dim3((2*DI)/64, MROWS/128), 256>>>(
            p_h, in_proj_w + (size_t)i*DM*2*DI, p_xz, MROWS, 2*DI, DM);

        conv_silu_kernel<<<BSZ*256, DI>>>(conv_w + (size_t)i*DI*4, conv_b + (size_t)i*DI);

        // proj = u @ x_proj_w[i]  (8192x512 @ 512x48)
        gemm_tf32_cp<64><<<dim3(1, MROWS/64), 256>>>(
            p_u, x_proj_w + (size_t)i*DI*PROJC, p_proj, MROWS, PROJC, DI);

        scan_kernel<<<BSZ*32, 256>>>(A_log + (size_t)i*DI*NST, Dv + (size_t)i*DI,
                                     dt_w + (size_t)i*DTR*DI, dt_b + (size_t)i*DI);

        // out2 = ymod @ out_proj_w[i]  (8192x512 @ 512x256)
        gemm_tf32_cp<128><<<dim3(DM/64, MROWS/128), 256>>>(
            p_ymod, out_proj_w + (size_t)i*DI*DM, p_out2, MROWS, DM, DI);

        ln_kernel<<<MROWS/16, 512>>>(ln_g + (size_t)i*DM, ln_b + (size_t)i*DM);
    }

    pool_kernel<<<BSZ, DM>>>();
    dec_kernel<<<1, 128>>>(dec_w, dec_b, (float*)d_out);
}

// round 10
// speedup vs baseline: 1.2867x; 1.2387x over previous
#include <cuda_runtime.h>
#include <cuda_bf16.h>
#include <math.h>

// ---------------- Problem dims ----------------
#define NL    8
#define BSZ   8
#define LSEQ  1024
#define DM    256
#define DI    512
#define NST   16
#define DTR   16
#define PROJC 48
#define MROWS (BSZ*LSEQ)  // 8192

// ---------------- Device scratch ----------------
__device__ float g_h   [MROWS*DM];
__device__ float g_xz  [MROWS*2*DI];
__device__ float g_proj[MROWS*PROJC];
__device__ float g_ymod[MROWS*DI];
__device__ float g_out2[MROWS*DM];
__device__ float g_pooled[BSZ*DM];

// ---------------- helpers ----------------
__device__ __forceinline__ void mma_tf32(float& d0, float& d1, float& d2, float& d3,
                                         unsigned a0, unsigned a1, unsigned a2, unsigned a3,
                                         unsigned b0, unsigned b1) {
    asm volatile(
        "mma.sync.aligned.m16n8k8.row.col.f32.tf32.tf32.f32 "
        "{%0,%1,%2,%3}, {%4,%5,%6,%7}, {%8,%9}, {%0,%1,%2,%3};\n"
        : "+f"(d0), "+f"(d1), "+f"(d2), "+f"(d3)
        : "r"(a0), "r"(a1), "r"(a2), "r"(a3), "r"(b0), "r"(b1));
}
__device__ __forceinline__ void cp16(unsigned dst, const void* src) {
    asm volatile("cp.async.cg.shared.global [%0], [%1], 16;\n" :: "r"(dst), "l"(src));
}
__device__ __forceinline__ void cp_commit() { asm volatile("cp.async.commit_group;\n"); }
__device__ __forceinline__ void cp_wait0()  { asm volatile("cp.async.wait_group 0;\n"); }
__device__ __forceinline__ void cp_wait1()  { asm volatile("cp.async.wait_group 1;\n"); }
__device__ __forceinline__ void cp_wait2()  { asm volatile("cp.async.wait_group 2;\n"); }

// ---------------- Encoder ----------------
__global__ void enc_kernel(const float* __restrict__ x,
                           const float* __restrict__ w,
                           const float* __restrict__ bb) {
    int bl = blockIdx.x;
    int m  = threadIdx.x;
    int b = bl >> 10, l = bl & 1023;
    float acc = bb[m];
#pragma unroll
    for (int c = 0; c < 3; c++)
        acc = fmaf(x[(b*3 + c)*LSEQ + l], w[c*DM + m], acc);
    g_h[bl*DM + m] = acc;
}

// ---------------- TF32 GEMM, cp.async 4-stage pipeline (in_proj / out_proj) -------
#define ASTR 20
#define BSTR 72
template<int BM>
__global__ void __launch_bounds__(256, 2)
gemm_tf32_cp(const float* __restrict__ A,
             const float* __restrict__ B,
             float* __restrict__ C,
             int M, int N, int K) {
    constexpr int AM = BM / 64;
    __shared__ unsigned As[4][BM*ASTR];
    __shared__ unsigned Bs[4][16*BSTR];

    const int tid  = threadIdx.x;
    const int lane = tid & 31;
    const int wid  = tid >> 5;
    const int wm   = wid & 3;
    const int wn   = wid >> 2;
    const int m0   = blockIdx.y * BM;
    const int n0   = blockIdx.x * 64;
    const int r = lane >> 2;
    const int c = lane & 3;

    const int bRow = tid >> 4;
    const int bNq  = tid & 15;
    const bool bOk = (n0 + bNq*4 + 3) < N;

    unsigned aBase[4], bBase[4];
#pragma unroll
    for (int s = 0; s < 4; s++) {
        aBase[s] = (unsigned)__cvta_generic_to_shared(&As[s][0]);
        bBase[s] = (unsigned)__cvta_generic_to_shared(&Bs[s][0]);
    }

    auto loadTile = [&](int t, int s) {
        int k0 = t * 16;
#pragma unroll
        for (int j = 0; j < AM; j++) {
            int slot = j*256 + tid;
            int row = slot >> 2, kq = slot & 3;
            cp16(aBase[s] + (row*ASTR + kq*4)*4,
                 A + (size_t)(m0 + row)*K + k0 + kq*4);
        }
        if (bOk)
            cp16(bBase[s] + (bRow*BSTR + bNq*4)*4,
                 B + (size_t)(k0 + bRow)*N + n0 + bNq*4);
        cp_commit();
    };

    float acc[AM][4][4] = {};
    const int T = K >> 4;

    loadTile(0, 0); loadTile(1, 1); loadTile(2, 2);

    for (int t = 0; t < T; t++) {
        int cur = t & 3;
        cp_wait2();
        __syncthreads();
        if (t + 3 < T) loadTile(t + 3, (t + 3) & 3);
        else           cp_commit();

        const unsigned* Ab = As[cur];
        const unsigned* Bb = Bs[cur];
#pragma unroll
        for (int kk = 0; kk < 16; kk += 8) {
            unsigned af[AM][4], bf[4][2];
#pragma unroll
            for (int am = 0; am < AM; am++) {
                int mrow = wm*(BM/4) + am*16;
                af[am][0] = Ab[(mrow + r    )*ASTR + kk + c    ];
                af[am][1] = Ab[(mrow + r + 8)*ASTR + kk + c    ];
                af[am][2] = Ab[(mrow + r    )*ASTR + kk + c + 4];
                af[am][3] = Ab[(mrow + r + 8)*ASTR + kk + c + 4];
            }
#pragma unroll
            for (int bn = 0; bn < 4; bn++) {
                int ncol = wn*32 + bn*8 + r;
                bf[bn][0] = Bb[(kk + c    )*BSTR + ncol];
                bf[bn][1] = Bb[(kk + c + 4)*BSTR + ncol];
            }
#pragma unroll
            for (int am = 0; am < AM; am++)
#pragma unroll
                for (int bn = 0; bn < 4; bn++)
                    mma_tf32(acc[am][bn][0], acc[am][bn][1], acc[am][bn][2], acc[am][bn][3],
                             af[am][0], af[am][1], af[am][2], af[am][3],
                             bf[bn][0], bf[bn][1]);
        }
    }

#pragma unroll
    for (int am = 0; am < AM; am++) {
#pragma unroll
        for (int bn = 0; bn < 4; bn++) {
            int m = m0 + wm*(BM/4) + am*16 + r;
            int n = n0 + wn*32 + bn*8 + 2*c;
            if (n + 1 < N) {
                *(float2*)(C + (size_t)m*N + n)       = make_float2(acc[am][bn][0], acc[am][bn][1]);
                *(float2*)(C + (size_t)(m + 8)*N + n) = make_float2(acc[am][bn][2], acc[am][bn][3]);
            } else if (n < N) {
                C[(size_t)m*N + n]       = acc[am][bn][0];
                C[(size_t)(m + 8)*N + n] = acc[am][bn][2];
            }
        }
    }
}

// ---------------- x_proj GEMM with fused conv+SiLU on the A path ----------------
// proj[8192,48] = silu(causal_conv(xz[:, :512])) @ W[512,48]
// A tile: stage raw xz rows (m0-3 .. m0+63) x 16 k-cols, convert to u in SMEM.
#define RSTR 20
__global__ void __launch_bounds__(256)
xproj_conv_gemm(const float* __restrict__ xz,
                const float* __restrict__ W,
                float* __restrict__ Cout,
                const float* __restrict__ cw,
                const float* __restrict__ cb) {
    __shared__ unsigned As[64*RSTR];       // u (fp32 bits)     5.1 KB
    __shared__ float    Raw[3][67*RSTR];   // raw xz + halo    16.1 KB
    __shared__ unsigned Bs[3][16*BSTR];    //                  13.8 KB
    __shared__ float    scw[DI*4];         // conv w            8.2 KB
    __shared__ float    scb[DI];           // conv b            2.0 KB

    const int tid  = threadIdx.x;
    const int lane = tid & 31;
    const int wid  = tid >> 5;
    const int wm   = wid & 3;
    const int wn   = wid >> 2;
    const int m0   = blockIdx.y * 64;
    const int r = lane >> 2;
    const int c = lane & 3;

    // zero all Bs (covers N=48 pad), load conv weights
    for (int i = tid; i < 3*16*BSTR; i += 256) (&Bs[0][0])[i] = 0u;
    for (int i = tid; i < DI*4; i += 256) scw[i] = cw[i];
    for (int i = tid; i < DI;   i += 256) scb[i] = cb[i];
    const bool hz = (m0 & 1023) == 0;      // halo crosses batch start -> zeros
    if (hz) {
#pragma unroll
        for (int s = 0; s < 3; s++)
            if (tid < 48) Raw[s][(tid >> 4)*RSTR + (tid & 15)] = 0.f;
    }
    __syncthreads();

    const int i1 = tid >> 2, q1 = tid & 3;
    const int bRow = tid >> 4;
    const int bNq  = tid & 15;
    const bool bOk = bNq < 12;             // 12*4 = 48 cols

    unsigned rawB[3], bsB[3];
#pragma unroll
    for (int s = 0; s < 3; s++) {
        rawB[s] = (unsigned)__cvta_generic_to_shared(&Raw[s][0]);
        bsB[s]  = (unsigned)__cvta_generic_to_shared(&Bs[s][0]);
    }

    auto loadT = [&](int t, int s) {
        int k0 = t * 16;
        if (!hz || i1 >= 3)
            cp16(rawB[s] + (i1*RSTR + q1*4)*4,
                 xz + (size_t)(m0 - 3 + i1)*(2*DI) + k0 + q1*4);
        if (tid < 12) {
            int i2 = 64 + (tid >> 2);
            cp16(rawB[s] + (i2*RSTR + (tid & 3)*4)*4,
                 xz + (size_t)(m0 - 3 + i2)*(2*DI) + k0 + (tid & 3)*4);
        }
        if (bOk)
            cp16(bsB[s] + (bRow*BSTR + bNq*4)*4,
                 W + (size_t)(k0 + bRow)*PROJC + bNq*4);
        cp_commit();
    };

    float acc[4][4] = {};
    const int T = DI >> 4;   // 32

    loadT(0, 0); loadT(1, 1);

    for (int t = 0; t < T; t++) {
        int cur = t % 3;
        cp_wait1();
        __syncthreads();                    // raw/Bs ready; prev mma done (As reusable)
        if (t + 2 < T) loadT(t + 2, (t + 2) % 3);
        else           cp_commit();

        // convert raw -> u  (each thread: 1 row x 4 cols)
        {
            const float* R = Raw[cur];
            int row = tid >> 2;
            int cb4 = (tid & 3) * 4;
#pragma unroll
            for (int j = 0; j < 4; j++) {
                int cc = cb4 + j;
                int d  = t*16 + cc;
                float a = scb[d];
#pragma unroll
                for (int k = 0; k < 4; k++)
                    a = fmaf(R[(row + k)*RSTR + cc], scw[d*4 + k], a);
                a = a / (1.f + __expf(-a));
                As[row*RSTR + cc] = __float_as_uint(a);
            }
        }
        __syncthreads();

        const unsigned* Bb = Bs[cur];
#pragma unroll
        for (int kk = 0; kk < 16; kk += 8) {
            unsigned af[4], bf[4][2];
            {
                int mrow = wm*16;
                af[0] = As[(mrow + r    )*RSTR + kk + c    ];
                af[1] = As[(mrow + r + 8)*RSTR + kk + c    ];
                af[2] = As[(mrow + r    )*RSTR + kk + c + 4];
                af[3] = As[(mrow + r + 8)*RSTR + kk + c + 4];
            }
#pragma unroll
            for (int bn = 0; bn < 4; bn++) {
                int ncol = wn*32 + bn*8 + r;
                bf[bn][0] = Bb[(kk + c    )*BSTR + ncol];
                bf[bn][1] = Bb[(kk + c + 4)*BSTR + ncol];
            }
#pragma unroll
            for (int bn = 0; bn < 4; bn++)
                mma_tf32(acc[bn][0], acc[bn][1], acc[bn][2], acc[bn][3],
                         af[0], af[1], af[2], af[3],
                         bf[bn][0], bf[bn][1]);
        }
    }

#pragma unroll
    for (int bn = 0; bn < 4; bn++) {
        int m = m0 + wm*16 + r;
        int n = wn*32 + bn*8 + 2*c;
        if (n + 1 < PROJC) {
            *(float2*)(Cout + (size_t)m*PROJC + n)       = make_float2(acc[bn][0], acc[bn][1]);
            *(float2*)(Cout + (size_t)(m + 8)*PROJC + n) = make_float2(acc[bn][2], acc[bn][3]);
        } else if (n < PROJC) {
            Cout[(size_t)m*PROJC + n]       = acc[bn][0];
            Cout[(size_t)(m + 8)*PROJC + n] = acc[bn][2];
        }
    }
}

// ---------------- Fused conv + dt + selective scan + gate ----------------
// Block = 256 thr = 16 halfwarp channels (batch b, 16 consecutive d).
// Per 64-step chunk: stage raw xz (x part + 3 halo rows), z, proj via cp.async;
// compute u = silu(conv) and gate = silu(z) in parallel; serial loop is lean.
#define SCH 64
#define SPSTR 52
__global__ void __launch_bounds__(256)
scan_kernel(const float* __restrict__ A_log,
            const float* __restrict__ Dv,
            const float* __restrict__ dtw,
            const float* __restrict__ dtb,
            const float* __restrict__ cw,
            const float* __restrict__ cb) {
    __shared__ float sp[2][SCH*SPSTR];   // proj rows            26.6 KB
    __shared__ float rx[2][67*16];       // raw xz x-part + halo  8.6 KB
    __shared__ float sz[2][SCH*16];      // z -> gate             8.2 KB
    __shared__ float su2[SCH*16];        // u; reused as output   4.1 KB

    const int b  = blockIdx.x >> 5;
    const int d0 = (blockIdx.x & 31) * 16;
    const int tid = threadIdx.x;
    const int hw = tid >> 4;
    const int n  = tid & 15;
    const int d  = d0 + hw;
    const int lane = tid & 31;
    const int hbase = lane & 16;
    const int blbase = b << 10;

    const int rl = tid >> 2;
    const int rq = tid & 3;

    // conv weights for this thread's 4 convert columns
    const int ccol = (tid & 3) * 4;
    float wv[4][4], bv[4];
#pragma unroll
    for (int j = 0; j < 4; j++) {
        bv[j] = cb[d0 + ccol + j];
#pragma unroll
        for (int k = 0; k < 4; k++)
            wv[j][k] = cw[(d0 + ccol + j)*4 + k];
    }

    // zero halo rows of rx[0] (chunk 0 has no predecessor rows)
    if (tid < 48) rx[0][tid] = 0.f;

    unsigned spB[2], rxB[2], szB[2];
#pragma unroll
    for (int s = 0; s < 2; s++) {
        spB[s] = (unsigned)__cvta_generic_to_shared(&sp[s][0]);
        rxB[s] = (unsigned)__cvta_generic_to_shared(&rx[s][0]);
        szB[s] = (unsigned)__cvta_generic_to_shared(&sz[s][0]);
    }

    auto loadChunk = [&](int c0, int buf) {
        if (c0 != 0 || rl >= 3)
            cp16(rxB[buf] + (rl*16 + rq*4)*4,
                 g_xz + (size_t)(blbase + c0 - 3 + rl)*(2*DI) + d0 + rq*4);
        if (tid < 12) {
            int i2 = 64 + (tid >> 2);
            cp16(rxB[buf] + (i2*16 + (tid & 3)*4)*4,
                 g_xz + (size_t)(blbase + c0 - 3 + i2)*(2*DI) + d0 + (tid & 3)*4);
        }
        cp16(szB[buf] + (rl*16 + rq*4)*4,
             g_xz + (size_t)(blbase + c0 + rl)*(2*DI) + DI + d0 + rq*4);
#pragma unroll
        for (int k = 0; k < 3; k++) {
            int s = tid + k*256;
            int l = s / 12, q = s - l*12;
            cp16(spB[buf] + (l*SPSTR + q*4)*4,
                 g_proj + (size_t)(blbase + c0 + l)*PROJC + q*4);
        }
        cp_commit();
    };

    float wdt[DTR];
#pragma unroll
    for (int r = 0; r < DTR; r++) wdt[r] = dtw[r*DI + d];
    const float dtbv = dtb[d];
    const float Ad = -__expf(A_log[d*NST + n]);
    const float Dd = Dv[d];
    float state = 0.f;

    loadChunk(0, 0);

    for (int cc = 0; cc < LSEQ/SCH; cc++) {
        int buf = cc & 1;
        if (cc + 1 < LSEQ/SCH) { loadChunk((cc+1)*SCH, buf ^ 1); cp_wait1(); }
        else                   { cp_wait0(); }
        __syncthreads();

        const float* P = sp[buf];
        const float* X = rx[buf];
        float*       Z = sz[buf];

        // dt for step l = j*16 + n (register-only)
        float dtv4[4];
#pragma unroll
        for (int j = 0; j < 4; j++) {
            float a = dtbv;
            const float* row = &P[(j*16 + n)*SPSTR];
#pragma unroll
            for (int r = 0; r < DTR; r++) a = fmaf(row[r], wdt[r], a);
            dtv4[j] = (a > 20.f) ? a : log1pf(__expf(a));
        }

        // convert: u = silu(conv(x)), gate = silu(z)  (1 row x 4 cols per thread)
        {
            int row = rl;
#pragma unroll
            for (int j = 0; j < 4; j++) {
                int c2 = ccol + j;
                float a = bv[j];
#pragma unroll
                for (int k = 0; k < 4; k++)
                    a = fmaf(X[(row + k)*16 + c2], wv[j][k], a);
                su2[row*16 + c2] = a / (1.f + __expf(-a));
                float zz = Z[row*16 + c2];
                Z[row*16 + c2] = zz / (1.f + __expf(-zz));
            }
        }
        __syncthreads();

#pragma unroll 4
        for (int l = 0; l < SCH; l++) {
            float dtv = __shfl_sync(0xffffffffu, dtv4[l >> 4], hbase + (l & 15), 32);
            float uv = su2[l*16 + hw];
            float Bv = P[l*SPSTR + DTR + n];
            float Cv = P[l*SPSTR + DTR + NST + n];
            state = fmaf(__expf(dtv*Ad), state, dtv*uv*Bv);
            float p = state * Cv;
            p += __shfl_xor_sync(0xffffffffu, p, 8);
            p += __shfl_xor_sync(0xffffffffu, p, 4);
            p += __shfl_xor_sync(0xffffffffu, p, 2);
            p += __shfl_xor_sync(0xffffffffu, p, 1);
            if (n == 0)
                su2[l*16 + hw] = (p + uv*Dd) * Z[l*16 + hw];  // overwrite u slot (read-before-write)
        }
        __syncthreads();

        {
            float4 v = *(const float4*)&su2[rl*16 + rq*4];
            *(float4*)(g_ymod + (size_t)(blbase + cc*SCH + rl)*DI + d0 + rq*4) = v;
        }
    }
}

// ---------------- Residual add + LayerNorm: warp-per-row, float4 ----------------
__global__ void __launch_bounds__(512)
ln_kernel(const float* __restrict__ gamma,
          const float* __restrict__ beta) {
    int wid  = threadIdx.x >> 5;
    int lane = threadIdx.x & 31;
    int bl   = blockIdx.x * 16 + wid;
    int col  = lane * 8;

    const float4* o4 = (const float4*)(g_out2 + (size_t)bl*DM + col);
    const float4* h4 = (const float4*)(g_h    + (size_t)bl*DM + col);
    float t[8];
    float4 a = o4[0], b = h4[0];
    t[0]=a.x+b.x; t[1]=a.y+b.y; t[2]=a.z+b.z; t[3]=a.w+b.w;
    a = o4[1]; b = h4[1];
    t[4]=a.x+b.x; t[5]=a.y+b.y; t[6]=a.z+b.z; t[7]=a.w+b.w;

    float v1 = 0.f, v2 = 0.f;
#pragma unroll
    for (int i = 0; i < 8; i++) { v1 += t[i]; v2 = fmaf(t[i], t[i], v2); }
#pragma unroll
    for (int o = 16; o > 0; o >>= 1) {
        v1 += __shfl_xor_sync(0xffffffffu, v1, o);
        v2 += __shfl_xor_sync(0xffffffffu, v2, o);
    }
    float mean = v1 * (1.f/DM);
    float var  = v2 * (1.f/DM) - mean*mean;
    float rs = rsqrtf(var + 1e-5f);

    float4 g0 = *(const float4*)(gamma + col);
    float4 g1 = *(const float4*)(gamma + col + 4);
    float4 b0 = *(const float4*)(beta  + col);
    float4 b1 = *(const float4*)(beta  + col + 4);

    float4 r0, r1;
    r0.x = (t[0]-mean)*rs*g0.x + b0.x;
    r0.y = (t[1]-mean)*rs*g0.y + b0.y;
    r0.z = (t[2]-mean)*rs*g0.z + b0.z;
    r0.w = (t[3]-mean)*rs*g0.w + b0.w;
    r1.x = (t[4]-mean)*rs*g1.x + b1.x;
    r1.y = (t[5]-mean)*rs*g1.y + b1.y;
    r1.z = (t[6]-mean)*rs*g1.z + b1.z;
    r1.w = (t[7]-mean)*rs*g1.w + b1.w;

    float4* out4 = (float4*)(g_h + (size_t)bl*DM + col);
    out4[0] = r0;
    out4[1] = r1;
}

// ---------------- Mean pool ----------------
__global__ void pool_kernel() {
    int b = blockIdx.x;
    int m = threadIdx.x;
    float s = 0.f;
    for (int l = 0; l < LSEQ; l++)
        s += g_h[(size_t)((b << 10) + l)*DM + m];
    g_pooled[b*DM + m] = s * (1.f/LSEQ);
}

// ---------------- Decoder ----------------
__global__ void dec_kernel(const float* __restrict__ w,
                           const float* __restrict__ bb,
                           float* __restrict__ out) {
    int i = threadIdx.x;
    if (i < BSZ*10) {
        int b = i / 10, o = i % 10;
        float acc = bb[o];
#pragma unroll 8
        for (int m = 0; m < DM; m++)
            acc = fmaf(g_pooled[b*DM + m], w[m*10 + o], acc);
        out[i] = acc;
    }
}

// ---------------- Launch ----------------
extern "C" void kernel_launch(void* const* d_in, const int* in_sizes, int n_in,
                              void* d_out, int out_size) {
    const float* x         = (const float*)d_in[0];
    const float* enc_w     = (const float*)d_in[1];
    const float* enc_b     = (const float*)d_in[2];
    const float* in_proj_w = (const float*)d_in[3];
    const float* conv_w    = (const float*)d_in[4];
    const float* conv_b    = (const float*)d_in[5];
    const float* x_proj_w  = (const float*)d_in[6];
    const float* dt_w      = (const float*)d_in[7];
    const float* dt_b      = (const float*)d_in[8];
    const float* A_log     = (const float*)d_in[9];
    const float* Dv        = (const float*)d_in[10];
    const float* out_proj_w= (const float*)d_in[11];
    const float* ln_g      = (const float*)d_in[12];
    const float* ln_b      = (const float*)d_in[13];
    const float* dec_w     = (const float*)d_in[14];
    const float* dec_b     = (const float*)d_in[15];

    float *p_h, *p_xz, *p_proj, *p_ymod, *p_out2;
    cudaGetSymbolAddress((void**)&p_h,    g_h);
    cudaGetSymbolAddress((void**)&p_xz,   g_xz);
    cudaGetSymbolAddress((void**)&p_proj, g_proj);
    cudaGetSymbolAddress((void**)&p_ymod, g_ymod);
    cudaGetSymbolAddress((void**)&p_out2, g_out2);

    enc_kernel<<<MROWS, DM>>>(x, enc_w, enc_b);

    for (int i = 0; i < NL; i++) {
        // xz = h @ in_proj_w[i]   (8192x256 @ 256x1024)
        gemm_tf32_cp<128><<<dim3((2*DI)/64, MROWS/128), 256>>>(
            p_h, in_proj_w + (size_t)i*DM*2*DI, p_xz, MROWS, 2*DI, DM);

        // proj = silu(conv(xz_x)) @ x_proj_w[i]  (conv fused into A staging)
        xproj_conv_gemm<<<dim3(1, MROWS/64), 256>>>(
            p_xz, x_proj_w + (size_t)i*DI*PROJC, p_proj,
            conv_w + (size_t)i*DI*4, conv_b + (size_t)i*DI);

        // fused conv + dt + selective scan + D skip + silu(z) gate
        scan_kernel<<<BSZ*32, 256>>>(A_log + (size_t)i*DI*NST, Dv + (size_t)i*DI,
                                     dt_w + (size_t)i*DTR*DI, dt_b + (size_t)i*DI,
                                     conv_w + (size_t)i*DI*4, conv_b + (size_t)i*DI);

        // out2 = ymod @ out_proj_w[i]  (8192x512 @ 512x256)
        gemm_tf32_cp<128><<<dim3(DM/64, MROWS/128), 256>>>(
            p_ymod, out_proj_w + (size_t)i*DI*DM, p_out2, MROWS, DM, DI);

        // h = layernorm(out2 + h)
        ln_kernel<<<MROWS/16, 512>>>(ln_g + (size_t)i*DM, ln_b + (size_t)i*DM);
    }

    pool_kernel<<<BSZ, DM>>>();
    dec_kernel<<<1, 128>>>(dec_w, dec_b, (float*)d_out);
}